// round 9
// baseline (speedup 1.0000x reference)
#include <cuda_runtime.h>
#include <math.h>
#include <stdint.h>

#define Nn 10000
#define Ee 160000
#define NFd 5
#define EFd 3
#define Hh 8
#define Cc 128
#define HCd 1024
#define Gg 16

// ---------------- scratch -----------------------------------------------
__device__ float g_xl[Nn * HCd];
__device__ float g_hA[Nn * HCd];
__device__ float g_hB[Nn * HCd];
__device__ float g_Wr[HCd * HCd];
__device__ float g_asrc[Nn * Hh];
__device__ float g_adst[Nn * Hh];
__device__ float g_loop[Nn * EFd];
__device__ float g_loopsum[Nn * EFd];
__device__ int   g_deg[Nn];
__device__ int   g_off[Nn + 1];
__device__ int   g_cur[Nn];
__device__ int   g_eid[Ee];
__device__ int   g_csrc[Ee];
__device__ float g_v[EFd * Hh];
__device__ float g_h4[Nn * Cc];
__device__ int   g_gstart[Gg];
__device__ int   g_gcnt[Gg];

__device__ __forceinline__ float lrelu(float x) { return x > 0.f ? x : 0.2f * x; }

__device__ __forceinline__ float tf32r(float f) {
    uint32_t r;
    asm("cvt.rna.tf32.f32 %0, %1;" : "=r"(r) : "f"(f));
    return __uint_as_float(r);
}

// ---------------- precompute --------------------------------------------
__global__ void k_initg() {
    int g = threadIdx.x;
    if (g < Gg) g_gstart[g] = Nn;
}

__global__ void k_deg(const int* __restrict__ ei, const float* __restrict__ ea) {
    int e = blockIdx.x * blockDim.x + threadIdx.x;
    if (e >= Ee) return;
    int d = ei[Ee + e];
    atomicAdd(&g_deg[d], 1);
    atomicAdd(&g_loopsum[d * 3 + 0], ea[e * 3 + 0]);
    atomicAdd(&g_loopsum[d * 3 + 1], ea[e * 3 + 1]);
    atomicAdd(&g_loopsum[d * 3 + 2], ea[e * 3 + 2]);
}

__global__ void k_scan() {
    __shared__ int tmp[256];
    __shared__ int carry;
    if (threadIdx.x == 0) { carry = 0; g_off[0] = 0; }
    __syncthreads();
    for (int base = 0; base < Nn; base += 256) {
        int i = base + threadIdx.x;
        int v = (i < Nn) ? g_deg[i] : 0;
        tmp[threadIdx.x] = v;
        __syncthreads();
        for (int s = 1; s < 256; s <<= 1) {
            int t = (threadIdx.x >= s) ? tmp[threadIdx.x - s] : 0;
            __syncthreads();
            tmp[threadIdx.x] += t;
            __syncthreads();
        }
        if (i < Nn) g_off[i + 1] = carry + tmp[threadIdx.x];
        __syncthreads();
        if (threadIdx.x == 0) carry += tmp[255];
        __syncthreads();
    }
}

__global__ void k_fill(const int* __restrict__ ei) {
    int e = blockIdx.x * blockDim.x + threadIdx.x;
    if (e >= Ee) return;
    int d = ei[Ee + e];
    int p = atomicAdd(&g_cur[d], 1);
    int slot = g_off[d] + p;
    g_eid[slot] = e;
    g_csrc[slot] = ei[e];
}

__global__ void k_loop() {
    int n = blockIdx.x * blockDim.x + threadIdx.x;
    if (n >= Nn) return;
    float inv = 1.f / (float)max(g_deg[n], 1);
    g_loop[n * 3 + 0] = g_loopsum[n * 3 + 0] * inv;
    g_loop[n * 3 + 1] = g_loopsum[n * 3 + 1] * inv;
    g_loop[n * 3 + 2] = g_loopsum[n * 3 + 2] * inv;
}

__global__ void k_bounds(const int* __restrict__ batch) {
    int n = blockIdx.x * blockDim.x + threadIdx.x;
    if (n >= Nn) return;
    int b = batch[n];
    atomicAdd(&g_gcnt[b], 1);
    atomicMin(&g_gstart[b], n);
}

// ---------------- layer-1 GEMM (K = 5) ----------------------------------
__global__ void k_gemm_small(const float* __restrict__ x, const float* __restrict__ W,
                             float* __restrict__ out) {
    int idx = blockIdx.x * blockDim.x + threadIdx.x;
    if (idx >= Nn * HCd) return;
    int n = idx >> 10, j = idx & 1023;
    float s = 0.f;
#pragma unroll
    for (int f = 0; f < NFd; f++) s += x[n * NFd + f] * W[f * HCd + j];
    out[idx] = s;
}

// ---------------- tf32 rounding for W -----------------------------------
__global__ void k_round(const float* __restrict__ W, float* __restrict__ Wr) {
    int i = blockIdx.x * blockDim.x + threadIdx.x;
    if (i < HCd * HCd) Wr[i] = tf32r(W[i]);
}

// ---------------- tf32 mma.sync GEMM (2-stage) --------------------------
#define MM_BK 32
#define MM_NT (HCd / MM_BK)
#define MM_ASTR 36
#define MM_BSTR 136
#define MM_STAGEF (128 * MM_ASTR + MM_BK * MM_BSTR)
#define MM_SMEM (2 * MM_STAGEF * 4)

__device__ __forceinline__ uint32_t s2u(const void* p) {
    uint32_t a;
    asm("{ .reg .u64 t; cvta.to.shared.u64 t, %1; cvt.u32.u64 %0, t; }" : "=r"(a) : "l"(p));
    return a;
}

__device__ __forceinline__ void mma8(float* c, const uint32_t* a, const uint32_t* b) {
    asm volatile(
        "mma.sync.aligned.m16n8k8.row.col.f32.tf32.tf32.f32 "
        "{%0,%1,%2,%3}, {%4,%5,%6,%7}, {%8,%9}, {%0,%1,%2,%3};"
        : "+f"(c[0]), "+f"(c[1]), "+f"(c[2]), "+f"(c[3])
        : "r"(a[0]), "r"(a[1]), "r"(a[2]), "r"(a[3]), "r"(b[0]), "r"(b[1]));
}

__global__ __launch_bounds__(256)
void k_mma(const float* __restrict__ A, const float* __restrict__ B,
           float* __restrict__ C, int M) {
    extern __shared__ __align__(16) float smem[];
    const int tid = threadIdx.x, wid = tid >> 5, lane = tid & 31;
    const int warp_m = wid & 3, warp_n = wid >> 2;
    const int row0 = blockIdx.y * 128, col0 = blockIdx.x * 128;
    const int lg = lane >> 2, lk = lane & 3;

    float acc[2][8][4];
#pragma unroll
    for (int mf = 0; mf < 2; mf++)
#pragma unroll
        for (int nf = 0; nf < 8; nf++)
#pragma unroll
            for (int q = 0; q < 4; q++) acc[mf][nf][q] = 0.f;

    const int ar = tid >> 3, ac = tid & 7;
    const int br = tid >> 3, bc = tid & 7;

    uint32_t sbase = s2u(smem);

    {
        int k0 = 0;
        float* sB = smem + 128 * MM_ASTR;
#pragma unroll
        for (int i = 0; i < 4; i++) {
            int r = ar + i * 32;
            uint32_t d = sbase + (r * MM_ASTR + ac * 4) * 4;
            int gr = row0 + r;
            if (gr < M)
                asm volatile("cp.async.cg.shared.global [%0], [%1], 16;"
                             :: "r"(d), "l"(A + (size_t)gr * HCd + k0 + ac * 4));
            else
                asm volatile("st.shared.v4.b32 [%0], {%1,%1,%1,%1};" :: "r"(d), "r"(0u) : "memory");
        }
#pragma unroll
        for (int j = 0; j < 4; j++) {
            uint32_t d = s2u(sB) + (br * MM_BSTR + bc * 4 + j * 32) * 4;
            asm volatile("cp.async.cg.shared.global [%0], [%1], 16;"
                         :: "r"(d), "l"(B + (size_t)(k0 + br) * HCd + col0 + bc * 4 + j * 32));
        }
        asm volatile("cp.async.commit_group;" ::: "memory");
    }

    for (int kt = 0; kt < MM_NT; kt++) {
        if (kt + 1 < MM_NT) {
            int k0 = (kt + 1) * MM_BK;
            float* sA = smem + ((kt + 1) & 1) * MM_STAGEF;
            float* sB = sA + 128 * MM_ASTR;
#pragma unroll
            for (int i = 0; i < 4; i++) {
                int r = ar + i * 32;
                uint32_t d = s2u(sA) + (r * MM_ASTR + ac * 4) * 4;
                int gr = row0 + r;
                if (gr < M)
                    asm volatile("cp.async.cg.shared.global [%0], [%1], 16;"
                                 :: "r"(d), "l"(A + (size_t)gr * HCd + k0 + ac * 4));
                else
                    asm volatile("st.shared.v4.b32 [%0], {%1,%1,%1,%1};" :: "r"(d), "r"(0u) : "memory");
            }
#pragma unroll
            for (int j = 0; j < 4; j++) {
                uint32_t d = s2u(sB) + (br * MM_BSTR + bc * 4 + j * 32) * 4;
                asm volatile("cp.async.cg.shared.global [%0], [%1], 16;"
                             :: "r"(d), "l"(B + (size_t)(k0 + br) * HCd + col0 + bc * 4 + j * 32));
            }
            asm volatile("cp.async.commit_group;" ::: "memory");
            asm volatile("cp.async.wait_group 1;" ::: "memory");
        } else {
            asm volatile("cp.async.commit_group;" ::: "memory");
            asm volatile("cp.async.wait_group 0;" ::: "memory");
        }
        __syncthreads();

        const float* sA = smem + (kt & 1) * MM_STAGEF;
        const float* sB = sA + 128 * MM_ASTR;
#pragma unroll
        for (int ks = 0; ks < 4; ks++) {
            uint32_t af[2][4], bf[8][2];
#pragma unroll
            for (int mf = 0; mf < 2; mf++) {
                int m = warp_m * 32 + mf * 16 + lg;
                int k = ks * 8 + lk;
                af[mf][0] = __float_as_uint(sA[m * MM_ASTR + k]);
                af[mf][1] = __float_as_uint(sA[(m + 8) * MM_ASTR + k]);
                af[mf][2] = __float_as_uint(sA[m * MM_ASTR + k + 4]);
                af[mf][3] = __float_as_uint(sA[(m + 8) * MM_ASTR + k + 4]);
            }
#pragma unroll
            for (int nf = 0; nf < 8; nf++) {
                int n = warp_n * 64 + nf * 8 + lg;
                int k = ks * 8 + lk;
                bf[nf][0] = __float_as_uint(sB[k * MM_BSTR + n]);
                bf[nf][1] = __float_as_uint(sB[(k + 4) * MM_BSTR + n]);
            }
#pragma unroll
            for (int mf = 0; mf < 2; mf++)
#pragma unroll
                for (int nf = 0; nf < 8; nf++) mma8(acc[mf][nf], af[mf], bf[nf]);
        }
        __syncthreads();
    }

#pragma unroll
    for (int mf = 0; mf < 2; mf++) {
        int r0 = row0 + warp_m * 32 + mf * 16 + lg;
        int r1 = r0 + 8;
#pragma unroll
        for (int nf = 0; nf < 8; nf++) {
            int ccol = col0 + warp_n * 64 + nf * 8 + 2 * lk;
            if (r0 < M) *(float2*)(C + (size_t)r0 * HCd + ccol) =
                make_float2(acc[mf][nf][0], acc[mf][nf][1]);
            if (r1 < M) *(float2*)(C + (size_t)r1 * HCd + ccol) =
                make_float2(acc[mf][nf][2], acc[mf][nf][3]);
        }
    }
}

// ---------------- attention pieces --------------------------------------
__global__ void k_attn(const float* __restrict__ xl, const float* __restrict__ a_s,
                       const float* __restrict__ a_d) {
    int gw = (blockIdx.x * blockDim.x + threadIdx.x) >> 5;
    int lane = threadIdx.x & 31;
    if (gw >= Nn * Hh) return;
    int n = gw >> 3, h = gw & 7;
    float4 xv = *(const float4*)(xl + (size_t)n * HCd + h * Cc + lane * 4);
    float4 sv = *(const float4*)(a_s + h * Cc + lane * 4);
    float4 dv = *(const float4*)(a_d + h * Cc + lane * 4);
    float s1 = xv.x * sv.x + xv.y * sv.y + xv.z * sv.z + xv.w * sv.w;
    float s2 = xv.x * dv.x + xv.y * dv.y + xv.z * dv.z + xv.w * dv.w;
#pragma unroll
    for (int o = 16; o; o >>= 1) {
        s1 += __shfl_xor_sync(0xffffffffu, s1, o);
        s2 += __shfl_xor_sync(0xffffffffu, s2, o);
    }
    if (lane == 0) {
        g_asrc[n * 8 + h] = s1;
        g_adst[n * 8 + h] = s2;
    }
}

__global__ void k_v(const float* __restrict__ We, const float* __restrict__ ae) {
    int w = threadIdx.x >> 5, lane = threadIdx.x & 31;
    if (w >= 24) return;
    int f = w >> 3, h = w & 7;
    float s = 0.f;
    for (int i = lane; i < Cc; i += 32) s += We[f * HCd + h * Cc + i] * ae[h * Cc + i];
#pragma unroll
    for (int o = 16; o; o >>= 1) s += __shfl_xor_sync(0xffffffffu, s, o);
    if (lane == 0) g_v[f * 8 + h] = s;
}

// block per node; two-phase chunked aggregation:
//   phase 1: 256 threads compute 32 edges x 8 heads weights (1 exp/thread)
//   phase 2: warp h sweeps the 32 edges; w via smem broadcast; float4 gather
__global__ __launch_bounds__(256) void k_agg(const float* __restrict__ xl,
                                             const float* __restrict__ ea,
                                             const float* __restrict__ bias,
                                             float* __restrict__ out, int mode) {
    __shared__ float w_s[256];
    __shared__ int sn_s[32];
    int n = blockIdx.x;
    int tid = threadIdx.x;
    int lane = tid & 31;
    int h = tid >> 5;            // phase-2 head (warp id)
    int hp = tid & 7;            // phase-1 head
    int col = h * Cc + lane * 4;

    float l0 = g_loop[n * 3 + 0], l1 = g_loop[n * 3 + 1], l2 = g_loop[n * 3 + 2];

    // phase-1 per-thread constants (head hp)
    float vp0 = g_v[hp], vp1 = g_v[8 + hp], vp2 = g_v[16 + hp];
    float adp = g_adst[n * 8 + hp];
    float cp = lrelu(g_asrc[n * 8 + hp] + adp + (l0 * vp0 + l1 * vp1 + l2 * vp2));

    // self contribution for this warp's head: exp(c - c) = 1
    float4 xv = *(const float4*)(xl + (size_t)n * HCd + col);
    float4 acc = xv;
    float den = 1.f;

    int s = g_off[n], tend = g_off[n + 1];
    for (int base = s; base < tend; base += 32) {
        int m = tend - base;
        if (m > 32) m = 32;
        // phase 1: compute weights
        int j = tid >> 3;
        if (j < m) {
            int e = g_eid[base + j];
            int sn = g_csrc[base + j];
            if (hp == 0) sn_s[j] = sn;
            float q0 = ea[e * 3 + 0], q1 = ea[e * 3 + 1], q2 = ea[e * 3 + 2];
            float aeh = q0 * vp0 + q1 * vp1 + q2 * vp2;
            float asn = g_asrc[sn * 8 + hp];
            w_s[tid] = __expf(lrelu(asn + adp + aeh) - cp);
        }
        __syncthreads();
        // phase 2: gather + accumulate
#pragma unroll 4
        for (int jj = 0; jj < m; jj++) {
            int sn = sn_s[jj];
            float w = w_s[jj * 8 + h];
            float4 xr = *(const float4*)(xl + (size_t)sn * HCd + col);
            acc.x += w * xr.x;
            acc.y += w * xr.y;
            acc.z += w * xr.z;
            acc.w += w * xr.w;
            den += w;
        }
        __syncthreads();
    }

    float inv = 1.f / (den + 1e-16f);
    float4 v = make_float4(acc.x * inv, acc.y * inv, acc.z * inv, acc.w * inv);
    if (mode == 0) {
        float4 b = *(const float4*)(bias + col);
        v.x += b.x; v.y += b.y; v.z += b.z; v.w += b.w;
        v.x = v.x > 0.f ? v.x : expm1f(v.x);
        v.y = v.y > 0.f ? v.y : expm1f(v.y);
        v.z = v.z > 0.f ? v.z : expm1f(v.z);
        v.w = v.w > 0.f ? v.w : expm1f(v.w);
        v.x = tf32r(v.x); v.y = tf32r(v.y); v.z = tf32r(v.z); v.w = tf32r(v.w);
    }
    *(float4*)(out + (size_t)n * HCd + col) = v;
}

__global__ void k_head(const float* __restrict__ tmp, const float* __restrict__ b4) {
    int idx = blockIdx.x * blockDim.x + threadIdx.x;
    if (idx >= Nn * Cc) return;
    int n = idx >> 7, c = idx & 127;
    float s = 0.f;
#pragma unroll
    for (int h = 0; h < 8; h++) s += tmp[(size_t)n * HCd + h * Cc + c];
    float v = s * 0.125f + b4[c];
    g_h4[idx] = v > 0.f ? v : expm1f(v);
}

__global__ void k_pool(const float* __restrict__ lw, const float* __restrict__ lb,
                       float* __restrict__ outp) {
    int g = blockIdx.x, c = threadIdx.x;
    int s = g_gstart[g], cnt = g_gcnt[g];
    float acc = 0.f;
    for (int i = 0; i < cnt; i++) acc += g_h4[(size_t)(s + i) * Cc + c];
    acc *= lw[c];
    __shared__ float red[128];
    red[c] = acc;
    __syncthreads();
    for (int o = 64; o; o >>= 1) {
        if (c < o) red[c] += red[c + o];
        __syncthreads();
    }
    if (c == 0) outp[g] = red[0] / fmaxf((float)cnt, 1.f) + lb[0];
}

// ---------------- launch -------------------------------------------------
static void* sym(const void* s) {
    void* p = nullptr;
    cudaGetSymbolAddress(&p, (const void*)s);
    return p;
}

extern "C" void kernel_launch(void* const* d_in, const int* in_sizes, int n_in,
                              void* d_out, int out_size) {
    (void)in_sizes; (void)n_in; (void)out_size;
    const float* x = (const float*)d_in[0];
    const int* ei = (const int*)d_in[1];
    const float* ea = (const float*)d_in[2];
    const int* batch = (const int*)d_in[3];
    const float *W[4], *We[4], *As_[4], *Ad_[4], *Ae_[4], *Bb[4];
    for (int l = 0; l < 4; l++) {
        W[l]   = (const float*)d_in[4 + 6 * l + 0];
        We[l]  = (const float*)d_in[4 + 6 * l + 1];
        As_[l] = (const float*)d_in[4 + 6 * l + 2];
        Ad_[l] = (const float*)d_in[4 + 6 * l + 3];
        Ae_[l] = (const float*)d_in[4 + 6 * l + 4];
        Bb[l]  = (const float*)d_in[4 + 6 * l + 5];
    }
    const float* lw = (const float*)d_in[28];
    const float* lb = (const float*)d_in[29];
    float* outp = (float*)d_out;

    float* xl = (float*)sym(&g_xl);
    float* hA = (float*)sym(&g_hA);
    float* hB = (float*)sym(&g_hB);
    float* Wr = (float*)sym(&g_Wr);

    cudaFuncSetAttribute(k_mma, cudaFuncAttributeMaxDynamicSharedMemorySize, MM_SMEM);

    cudaMemsetAsync(sym(&g_deg), 0, Nn * sizeof(int));
    cudaMemsetAsync(sym(&g_loopsum), 0, Nn * EFd * sizeof(float));
    cudaMemsetAsync(sym(&g_cur), 0, Nn * sizeof(int));
    cudaMemsetAsync(sym(&g_gcnt), 0, Gg * sizeof(int));
    k_initg<<<1, 32>>>();
    k_deg<<<(Ee + 255) / 256, 256>>>(ei, ea);
    k_scan<<<1, 256>>>();
    k_fill<<<(Ee + 255) / 256, 256>>>(ei);
    k_loop<<<(Nn + 255) / 256, 256>>>();
    k_bounds<<<(Nn + 255) / 256, 256>>>(batch);

    for (int l = 0; l < 4; l++) {
        const float* inp = (l == 0) ? x : ((l == 1) ? hA : ((l == 2) ? hB : hA));
        float* hout = (l == 0) ? hA : ((l == 1) ? hB : ((l == 2) ? hA : hB));

        if (l == 0) {
            k_gemm_small<<<(Nn * HCd + 255) / 256, 256>>>(x, W[0], xl);
        } else {
            k_round<<<(HCd * HCd + 255) / 256, 256>>>(W[l], Wr);
            k_mma<<<dim3(HCd / 128, (Nn + 127) / 128), 256, MM_SMEM>>>(inp, Wr, xl, Nn);
        }

        k_attn<<<(Nn * Hh * 32 + 255) / 256, 256>>>(xl, As_[l], Ad_[l]);
        k_v<<<1, 768>>>(We[l], Ae_[l]);
        k_agg<<<Nn, 256>>>(xl, ea, Bb[l], hout, (l < 3) ? 0 : 1);
        if (l == 3) k_head<<<(Nn * Cc + 255) / 256, 256>>>(hB, Bb[3]);
    }
    k_pool<<<Gg, 128>>>(lw, lb, outp);
}

// round 12
// speedup vs baseline: 1.4450x; 1.4450x over previous
#include <cuda_runtime.h>
#include <math.h>
#include <stdint.h>

#define Nn 10000
#define Ee 160000
#define NFd 5
#define EFd 3
#define Hh 8
#define Cc 128
#define HCd 1024
#define Gg 16

// ---------------- scratch -----------------------------------------------
__device__ float g_xl[Nn * HCd];
__device__ float g_hA[Nn * HCd];
__device__ float g_hB[Nn * HCd];
__device__ float g_Wr[HCd * HCd];
__device__ float g_asrc[Nn * Hh];
__device__ float g_adst[Nn * Hh];
__device__ float g_loop[Nn * EFd];
__device__ float g_loopsum[Nn * EFd];
__device__ int   g_deg[Nn];
__device__ int   g_off[Nn + 1];
__device__ int   g_cur[Nn];
__device__ int   g_csrc[Ee];
__device__ float4 g_cea4[Ee];        // CSR-ordered edge attrs (q0,q1,q2,0)
__device__ float g_v[EFd * Hh];
__device__ float g_h4[Nn * Cc];
__device__ int   g_gstart[Gg];
__device__ int   g_gcnt[Gg];

__device__ __forceinline__ float lrelu(float x) { return x > 0.f ? x : 0.2f * x; }

__device__ __forceinline__ float tf32r(float f) {
    uint32_t r;
    asm("cvt.rna.tf32.f32 %0, %1;" : "=r"(r) : "f"(f));
    return __uint_as_float(r);
}

// ---------------- precompute --------------------------------------------
__global__ void k_initg() {
    int g = threadIdx.x;
    if (g < Gg) g_gstart[g] = Nn;
}

__global__ void k_deg(const int* __restrict__ ei, const float* __restrict__ ea) {
    int e = blockIdx.x * blockDim.x + threadIdx.x;
    if (e >= Ee) return;
    int d = ei[Ee + e];
    atomicAdd(&g_deg[d], 1);
    atomicAdd(&g_loopsum[d * 3 + 0], ea[e * 3 + 0]);
    atomicAdd(&g_loopsum[d * 3 + 1], ea[e * 3 + 1]);
    atomicAdd(&g_loopsum[d * 3 + 2], ea[e * 3 + 2]);
}

__global__ void k_scan() {
    __shared__ int tmp[256];
    __shared__ int carry;
    if (threadIdx.x == 0) { carry = 0; g_off[0] = 0; }
    __syncthreads();
    for (int base = 0; base < Nn; base += 256) {
        int i = base + threadIdx.x;
        int v = (i < Nn) ? g_deg[i] : 0;
        tmp[threadIdx.x] = v;
        __syncthreads();
        for (int s = 1; s < 256; s <<= 1) {
            int t = (threadIdx.x >= s) ? tmp[threadIdx.x - s] : 0;
            __syncthreads();
            tmp[threadIdx.x] += t;
            __syncthreads();
        }
        if (i < Nn) g_off[i + 1] = carry + tmp[threadIdx.x];
        __syncthreads();
        if (threadIdx.x == 0) carry += tmp[255];
        __syncthreads();
    }
}

__global__ void k_fill(const int* __restrict__ ei, const float* __restrict__ ea) {
    int e = blockIdx.x * blockDim.x + threadIdx.x;
    if (e >= Ee) return;
    int d = ei[Ee + e];
    int p = atomicAdd(&g_cur[d], 1);
    int slot = g_off[d] + p;
    g_csrc[slot] = ei[e];
    g_cea4[slot] = make_float4(ea[e * 3 + 0], ea[e * 3 + 1], ea[e * 3 + 2], 0.f);
}

__global__ void k_loop() {
    int n = blockIdx.x * blockDim.x + threadIdx.x;
    if (n >= Nn) return;
    float inv = 1.f / (float)max(g_deg[n], 1);
    g_loop[n * 3 + 0] = g_loopsum[n * 3 + 0] * inv;
    g_loop[n * 3 + 1] = g_loopsum[n * 3 + 1] * inv;
    g_loop[n * 3 + 2] = g_loopsum[n * 3 + 2] * inv;
}

__global__ void k_bounds(const int* __restrict__ batch) {
    int n = blockIdx.x * blockDim.x + threadIdx.x;
    if (n >= Nn) return;
    int b = batch[n];
    atomicAdd(&g_gcnt[b], 1);
    atomicMin(&g_gstart[b], n);
}

// ---------------- layer-1 GEMM (K = 5) ----------------------------------
__global__ void k_gemm_small(const float* __restrict__ x, const float* __restrict__ W,
                             float* __restrict__ out) {
    int idx = blockIdx.x * blockDim.x + threadIdx.x;
    if (idx >= Nn * HCd) return;
    int n = idx >> 10, j = idx & 1023;
    float s = 0.f;
#pragma unroll
    for (int f = 0; f < NFd; f++) s += x[n * NFd + f] * W[f * HCd + j];
    out[idx] = s;
}

// ---------------- tf32 rounding for W -----------------------------------
__global__ void k_round(const float* __restrict__ W, float* __restrict__ Wr) {
    int i = blockIdx.x * blockDim.x + threadIdx.x;
    if (i < HCd * HCd) Wr[i] = tf32r(W[i]);
}

// ---------------- tf32 mma.sync GEMM (2-stage) --------------------------
#define MM_BK 32
#define MM_NT (HCd / MM_BK)
#define MM_ASTR 36
#define MM_BSTR 136
#define MM_STAGEF (128 * MM_ASTR + MM_BK * MM_BSTR)
#define MM_SMEM (2 * MM_STAGEF * 4)

__device__ __forceinline__ uint32_t s2u(const void* p) {
    uint32_t a;
    asm("{ .reg .u64 t; cvta.to.shared.u64 t, %1; cvt.u32.u64 %0, t; }" : "=r"(a) : "l"(p));
    return a;
}

__device__ __forceinline__ void mma8(float* c, const uint32_t* a, const uint32_t* b) {
    asm volatile(
        "mma.sync.aligned.m16n8k8.row.col.f32.tf32.tf32.f32 "
        "{%0,%1,%2,%3}, {%4,%5,%6,%7}, {%8,%9}, {%0,%1,%2,%3};"
        : "+f"(c[0]), "+f"(c[1]), "+f"(c[2]), "+f"(c[3])
        : "r"(a[0]), "r"(a[1]), "r"(a[2]), "r"(a[3]), "r"(b[0]), "r"(b[1]));
}

__global__ __launch_bounds__(256)
void k_mma(const float* __restrict__ A, const float* __restrict__ B,
           float* __restrict__ C, int M) {
    extern __shared__ __align__(16) float smem[];
    const int tid = threadIdx.x, wid = tid >> 5, lane = tid & 31;
    const int warp_m = wid & 3, warp_n = wid >> 2;
    const int row0 = blockIdx.y * 128, col0 = blockIdx.x * 128;
    const int lg = lane >> 2, lk = lane & 3;

    float acc[2][8][4];
#pragma unroll
    for (int mf = 0; mf < 2; mf++)
#pragma unroll
        for (int nf = 0; nf < 8; nf++)
#pragma unroll
            for (int q = 0; q < 4; q++) acc[mf][nf][q] = 0.f;

    const int ar = tid >> 3, ac = tid & 7;
    const int br = tid >> 3, bc = tid & 7;

    uint32_t sbase = s2u(smem);

    {
        int k0 = 0;
        float* sB = smem + 128 * MM_ASTR;
#pragma unroll
        for (int i = 0; i < 4; i++) {
            int r = ar + i * 32;
            uint32_t d = sbase + (r * MM_ASTR + ac * 4) * 4;
            int gr = row0 + r;
            if (gr < M)
                asm volatile("cp.async.cg.shared.global [%0], [%1], 16;"
                             :: "r"(d), "l"(A + (size_t)gr * HCd + k0 + ac * 4));
            else
                asm volatile("st.shared.v4.b32 [%0], {%1,%1,%1,%1};" :: "r"(d), "r"(0u) : "memory");
        }
#pragma unroll
        for (int j = 0; j < 4; j++) {
            uint32_t d = s2u(sB) + (br * MM_BSTR + bc * 4 + j * 32) * 4;
            asm volatile("cp.async.cg.shared.global [%0], [%1], 16;"
                         :: "r"(d), "l"(B + (size_t)(k0 + br) * HCd + col0 + bc * 4 + j * 32));
        }
        asm volatile("cp.async.commit_group;" ::: "memory");
    }

    for (int kt = 0; kt < MM_NT; kt++) {
        if (kt + 1 < MM_NT) {
            int k0 = (kt + 1) * MM_BK;
            float* sA = smem + ((kt + 1) & 1) * MM_STAGEF;
            float* sB = sA + 128 * MM_ASTR;
#pragma unroll
            for (int i = 0; i < 4; i++) {
                int r = ar + i * 32;
                uint32_t d = s2u(sA) + (r * MM_ASTR + ac * 4) * 4;
                int gr = row0 + r;
                if (gr < M)
                    asm volatile("cp.async.cg.shared.global [%0], [%1], 16;"
                                 :: "r"(d), "l"(A + (size_t)gr * HCd + k0 + ac * 4));
                else
                    asm volatile("st.shared.v4.b32 [%0], {%1,%1,%1,%1};" :: "r"(d), "r"(0u) : "memory");
            }
#pragma unroll
            for (int j = 0; j < 4; j++) {
                uint32_t d = s2u(sB) + (br * MM_BSTR + bc * 4 + j * 32) * 4;
                asm volatile("cp.async.cg.shared.global [%0], [%1], 16;"
                             :: "r"(d), "l"(B + (size_t)(k0 + br) * HCd + col0 + bc * 4 + j * 32));
            }
            asm volatile("cp.async.commit_group;" ::: "memory");
            asm volatile("cp.async.wait_group 1;" ::: "memory");
        } else {
            asm volatile("cp.async.commit_group;" ::: "memory");
            asm volatile("cp.async.wait_group 0;" ::: "memory");
        }
        __syncthreads();

        const float* sA = smem + (kt & 1) * MM_STAGEF;
        const float* sB = sA + 128 * MM_ASTR;
#pragma unroll
        for (int ks = 0; ks < 4; ks++) {
            uint32_t af[2][4], bf[8][2];
#pragma unroll
            for (int mf = 0; mf < 2; mf++) {
                int m = warp_m * 32 + mf * 16 + lg;
                int k = ks * 8 + lk;
                af[mf][0] = __float_as_uint(sA[m * MM_ASTR + k]);
                af[mf][1] = __float_as_uint(sA[(m + 8) * MM_ASTR + k]);
                af[mf][2] = __float_as_uint(sA[m * MM_ASTR + k + 4]);
                af[mf][3] = __float_as_uint(sA[(m + 8) * MM_ASTR + k + 4]);
            }
#pragma unroll
            for (int nf = 0; nf < 8; nf++) {
                int n = warp_n * 64 + nf * 8 + lg;
                int k = ks * 8 + lk;
                bf[nf][0] = __float_as_uint(sB[k * MM_BSTR + n]);
                bf[nf][1] = __float_as_uint(sB[(k + 4) * MM_BSTR + n]);
            }
#pragma unroll
            for (int mf = 0; mf < 2; mf++)
#pragma unroll
                for (int nf = 0; nf < 8; nf++) mma8(acc[mf][nf], af[mf], bf[nf]);
        }
        __syncthreads();
    }

#pragma unroll
    for (int mf = 0; mf < 2; mf++) {
        int r0 = row0 + warp_m * 32 + mf * 16 + lg;
        int r1 = r0 + 8;
#pragma unroll
        for (int nf = 0; nf < 8; nf++) {
            int ccol = col0 + warp_n * 64 + nf * 8 + 2 * lk;
            if (r0 < M) *(float2*)(C + (size_t)r0 * HCd + ccol) =
                make_float2(acc[mf][nf][0], acc[mf][nf][1]);
            if (r1 < M) *(float2*)(C + (size_t)r1 * HCd + ccol) =
                make_float2(acc[mf][nf][2], acc[mf][nf][3]);
        }
    }
}

// ---------------- attention pieces --------------------------------------
__global__ void k_attn(const float* __restrict__ xl, const float* __restrict__ a_s,
                       const float* __restrict__ a_d) {
    int gw = (blockIdx.x * blockDim.x + threadIdx.x) >> 5;
    int lane = threadIdx.x & 31;
    if (gw >= Nn * Hh) return;
    int n = gw >> 3, h = gw & 7;
    float4 xv = *(const float4*)(xl + (size_t)n * HCd + h * Cc + lane * 4);
    float4 sv = *(const float4*)(a_s + h * Cc + lane * 4);
    float4 dv = *(const float4*)(a_d + h * Cc + lane * 4);
    float s1 = xv.x * sv.x + xv.y * sv.y + xv.z * sv.z + xv.w * sv.w;
    float s2 = xv.x * dv.x + xv.y * dv.y + xv.z * dv.z + xv.w * dv.w;
#pragma unroll
    for (int o = 16; o; o >>= 1) {
        s1 += __shfl_xor_sync(0xffffffffu, s1, o);
        s2 += __shfl_xor_sync(0xffffffffu, s2, o);
    }
    if (lane == 0) {
        g_asrc[n * 8 + h] = s1;
        g_adst[n * 8 + h] = s2;
    }
}

__global__ void k_v(const float* __restrict__ We, const float* __restrict__ ae) {
    int w = threadIdx.x >> 5, lane = threadIdx.x & 31;
    if (w >= 24) return;
    int f = w >> 3, h = w & 7;
    float s = 0.f;
    for (int i = lane; i < Cc; i += 32) s += We[f * HCd + h * Cc + i] * ae[h * Cc + i];
#pragma unroll
    for (int o = 16; o; o >>= 1) s += __shfl_xor_sync(0xffffffffu, s, o);
    if (lane == 0) g_v[f * 8 + h] = s;
}

// block per node; warp = head; lane owns 4 consecutive cols.
// Warp-batched weights: lane j computes edge (base+j)'s weight for this
// warp's head (1 exp/lane, 3 LDG instr per 32 edges), then shfl-broadcast
// into the float4 gather loop. No barriers, no smem.
__global__ __launch_bounds__(256) void k_agg(const float* __restrict__ xl,
                                             const float* __restrict__ bias,
                                             float* __restrict__ out, int mode) {
    int n = blockIdx.x;
    int lane = threadIdx.x & 31;
    int h = threadIdx.x >> 5;
    int col = h * Cc + lane * 4;

    float vh0 = g_v[h], vh1 = g_v[8 + h], vh2 = g_v[16 + h];
    float adh = g_adst[n * 8 + h];
    float ash = g_asrc[n * 8 + h];
    float l0 = g_loop[n * 3 + 0], l1 = g_loop[n * 3 + 1], l2 = g_loop[n * 3 + 2];
    float c = lrelu(ash + adh + (l0 * vh0 + l1 * vh1 + l2 * vh2));

    // self contribution: exp(c - c) = 1
    float4 xv = *(const float4*)(xl + (size_t)n * HCd + col);
    float4 acc = xv;
    float den = 1.f;

    int s = g_off[n], tend = g_off[n + 1];
    for (int base = s; base < tend; base += 32) {
        int m = tend - base;
        if (m > 32) m = 32;
        // lane j computes weight of edge base+j for head h
        float w = 0.f;
        int sn = 0;
        if (lane < m) {
            sn = g_csrc[base + lane];
            float4 q = g_cea4[base + lane];
            float asn = g_asrc[sn * 8 + h];
            float aeh = q.x * vh0 + q.y * vh1 + q.z * vh2;
            w = __expf(lrelu(asn + adh + aeh) - c);
        }
        // broadcast + gather
#pragma unroll 4
        for (int jj = 0; jj < m; jj++) {
            float wj = __shfl_sync(0xffffffffu, w, jj);
            int snj = __shfl_sync(0xffffffffu, sn, jj);
            float4 xr = *(const float4*)(xl + (size_t)snj * HCd + col);
            acc.x += wj * xr.x;
            acc.y += wj * xr.y;
            acc.z += wj * xr.z;
            acc.w += wj * xr.w;
            den += wj;
        }
    }

    float inv = 1.f / (den + 1e-16f);
    float4 v = make_float4(acc.x * inv, acc.y * inv, acc.z * inv, acc.w * inv);
    if (mode == 0) {
        float4 b = *(const float4*)(bias + col);
        v.x += b.x; v.y += b.y; v.z += b.z; v.w += b.w;
        v.x = v.x > 0.f ? v.x : expm1f(v.x);
        v.y = v.y > 0.f ? v.y : expm1f(v.y);
        v.z = v.z > 0.f ? v.z : expm1f(v.z);
        v.w = v.w > 0.f ? v.w : expm1f(v.w);
        v.x = tf32r(v.x); v.y = tf32r(v.y); v.z = tf32r(v.z); v.w = tf32r(v.w);
    }
    *(float4*)(out + (size_t)n * HCd + col) = v;
}

__global__ void k_head(const float* __restrict__ tmp, const float* __restrict__ b4) {
    int idx = blockIdx.x * blockDim.x + threadIdx.x;
    if (idx >= Nn * Cc) return;
    int n = idx >> 7, c = idx & 127;
    float s = 0.f;
#pragma unroll
    for (int h = 0; h < 8; h++) s += tmp[(size_t)n * HCd + h * Cc + c];
    float v = s * 0.125f + b4[c];
    g_h4[idx] = v > 0.f ? v : expm1f(v);
}

__global__ void k_pool(const float* __restrict__ lw, const float* __restrict__ lb,
                       float* __restrict__ outp) {
    int g = blockIdx.x, c = threadIdx.x;
    int s = g_gstart[g], cnt = g_gcnt[g];
    float acc = 0.f;
    for (int i = 0; i < cnt; i++) acc += g_h4[(size_t)(s + i) * Cc + c];
    acc *= lw[c];
    __shared__ float red[128];
    red[c] = acc;
    __syncthreads();
    for (int o = 64; o; o >>= 1) {
        if (c < o) red[c] += red[c + o];
        __syncthreads();
    }
    if (c == 0) outp[g] = red[0] / fmaxf((float)cnt, 1.f) + lb[0];
}

// ---------------- launch -------------------------------------------------
static void* sym(const void* s) {
    void* p = nullptr;
    cudaGetSymbolAddress(&p, (const void*)s);
    return p;
}

extern "C" void kernel_launch(void* const* d_in, const int* in_sizes, int n_in,
                              void* d_out, int out_size) {
    (void)in_sizes; (void)n_in; (void)out_size;
    const float* x = (const float*)d_in[0];
    const int* ei = (const int*)d_in[1];
    const float* ea = (const float*)d_in[2];
    const int* batch = (const int*)d_in[3];
    const float *W[4], *We[4], *As_[4], *Ad_[4], *Ae_[4], *Bb[4];
    for (int l = 0; l < 4; l++) {
        W[l]   = (const float*)d_in[4 + 6 * l + 0];
        We[l]  = (const float*)d_in[4 + 6 * l + 1];
        As_[l] = (const float*)d_in[4 + 6 * l + 2];
        Ad_[l] = (const float*)d_in[4 + 6 * l + 3];
        Ae_[l] = (const float*)d_in[4 + 6 * l + 4];
        Bb[l]  = (const float*)d_in[4 + 6 * l + 5];
    }
    const float* lw = (const float*)d_in[28];
    const float* lb = (const float*)d_in[29];
    float* outp = (float*)d_out;

    float* xl = (float*)sym(&g_xl);
    float* hA = (float*)sym(&g_hA);
    float* hB = (float*)sym(&g_hB);
    float* Wr = (float*)sym(&g_Wr);

    cudaFuncSetAttribute(k_mma, cudaFuncAttributeMaxDynamicSharedMemorySize, MM_SMEM);

    cudaMemsetAsync(sym(&g_deg), 0, Nn * sizeof(int));
    cudaMemsetAsync(sym(&g_loopsum), 0, Nn * EFd * sizeof(float));
    cudaMemsetAsync(sym(&g_cur), 0, Nn * sizeof(int));
    cudaMemsetAsync(sym(&g_gcnt), 0, Gg * sizeof(int));
    k_initg<<<1, 32>>>();
    k_deg<<<(Ee + 255) / 256, 256>>>(ei, ea);
    k_scan<<<1, 256>>>();
    k_fill<<<(Ee + 255) / 256, 256>>>(ei, ea);
    k_loop<<<(Nn + 255) / 256, 256>>>();
    k_bounds<<<(Nn + 255) / 256, 256>>>(batch);

    for (int l = 0; l < 4; l++) {
        const float* inp = (l == 0) ? x : ((l == 1) ? hA : ((l == 2) ? hB : hA));
        float* hout = (l == 0) ? hA : ((l == 1) ? hB : ((l == 2) ? hA : hB));

        if (l == 0) {
            k_gemm_small<<<(Nn * HCd + 255) / 256, 256>>>(x, W[0], xl);
        } else {
            k_round<<<(HCd * HCd + 255) / 256, 256>>>(W[l], Wr);
            k_mma<<<dim3(HCd / 128, (Nn + 127) / 128), 256, MM_SMEM>>>(inp, Wr, xl, Nn);
        }

        k_attn<<<(Nn * Hh * 32 + 255) / 256, 256>>>(xl, As_[l], Ad_[l]);
        k_v<<<1, 768>>>(We[l], Ae_[l]);
        k_agg<<<Nn, 256>>>(xl, Bb[l], hout, (l < 3) ? 0 : 1);
        if (l == 3) k_head<<<(Nn * Cc + 255) / 256, 256>>>(hB, Bb[3]);
    }
    k_pool<<<Gg, 128>>>(lw, lb, outp);
}

// round 14
// speedup vs baseline: 1.7058x; 1.1806x over previous
#include <cuda_runtime.h>
#include <cuda_fp16.h>
#include <math.h>
#include <stdint.h>

#define Nn 10000
#define Ee 160000
#define NFd 5
#define EFd 3
#define Hh 8
#define Cc 128
#define HCd 1024
#define Gg 16

// ---------------- scratch -----------------------------------------------
__device__ float  g_xl[Nn * HCd];
__device__ __half g_hAh[Nn * HCd];    // half h buffers (GEMM inputs only)
__device__ __half g_hBh[Nn * HCd];
__device__ float  g_hf[Nn * HCd];     // layer-4 fp32 output (feeds k_head)
__device__ __half g_Wh[HCd * HCd];    // transposed half weights [n][k]
__device__ float g_asrc[Nn * Hh];
__device__ float g_adst[Nn * Hh];
__device__ float g_loop[Nn * EFd];
__device__ float g_loopsum[Nn * EFd];
__device__ int   g_deg[Nn];
__device__ int   g_off[Nn + 1];
__device__ int   g_cur[Nn];
__device__ int   g_csrc[Ee];
__device__ float4 g_cea4[Ee];        // CSR-ordered edge attrs (q0,q1,q2,0)
__device__ float g_v[EFd * Hh];
__device__ float g_h4[Nn * Cc];
__device__ int   g_gstart[Gg];
__device__ int   g_gcnt[Gg];

__device__ __forceinline__ float lrelu(float x) { return x > 0.f ? x : 0.2f * x; }

// ---------------- precompute --------------------------------------------
__global__ void k_initg() {
    int g = threadIdx.x;
    if (g < Gg) g_gstart[g] = Nn;
}

__global__ void k_deg(const int* __restrict__ ei, const float* __restrict__ ea) {
    int e = blockIdx.x * blockDim.x + threadIdx.x;
    if (e >= Ee) return;
    int d = ei[Ee + e];
    atomicAdd(&g_deg[d], 1);
    atomicAdd(&g_loopsum[d * 3 + 0], ea[e * 3 + 0]);
    atomicAdd(&g_loopsum[d * 3 + 1], ea[e * 3 + 1]);
    atomicAdd(&g_loopsum[d * 3 + 2], ea[e * 3 + 2]);
}

__global__ void k_scan() {
    __shared__ int tmp[256];
    __shared__ int carry;
    if (threadIdx.x == 0) { carry = 0; g_off[0] = 0; }
    __syncthreads();
    for (int base = 0; base < Nn; base += 256) {
        int i = base + threadIdx.x;
        int v = (i < Nn) ? g_deg[i] : 0;
        tmp[threadIdx.x] = v;
        __syncthreads();
        for (int s = 1; s < 256; s <<= 1) {
            int t = (threadIdx.x >= s) ? tmp[threadIdx.x - s] : 0;
            __syncthreads();
            tmp[threadIdx.x] += t;
            __syncthreads();
        }
        if (i < Nn) g_off[i + 1] = carry + tmp[threadIdx.x];
        __syncthreads();
        if (threadIdx.x == 0) carry += tmp[255];
        __syncthreads();
    }
}

__global__ void k_fill(const int* __restrict__ ei, const float* __restrict__ ea) {
    int e = blockIdx.x * blockDim.x + threadIdx.x;
    if (e >= Ee) return;
    int d = ei[Ee + e];
    int p = atomicAdd(&g_cur[d], 1);
    int slot = g_off[d] + p;
    g_csrc[slot] = ei[e];
    g_cea4[slot] = make_float4(ea[e * 3 + 0], ea[e * 3 + 1], ea[e * 3 + 2], 0.f);
}

__global__ void k_loop() {
    int n = blockIdx.x * blockDim.x + threadIdx.x;
    if (n >= Nn) return;
    float inv = 1.f / (float)max(g_deg[n], 1);
    g_loop[n * 3 + 0] = g_loopsum[n * 3 + 0] * inv;
    g_loop[n * 3 + 1] = g_loopsum[n * 3 + 1] * inv;
    g_loop[n * 3 + 2] = g_loopsum[n * 3 + 2] * inv;
}

__global__ void k_bounds(const int* __restrict__ batch) {
    int n = blockIdx.x * blockDim.x + threadIdx.x;
    if (n >= Nn) return;
    int b = batch[n];
    atomicAdd(&g_gcnt[b], 1);
    atomicMin(&g_gstart[b], n);
}

// ---------------- layer-1 GEMM (K = 5) ----------------------------------
__global__ void k_gemm_small(const float* __restrict__ x, const float* __restrict__ W,
                             float* __restrict__ out) {
    int idx = blockIdx.x * blockDim.x + threadIdx.x;
    if (idx >= Nn * HCd) return;
    int n = idx >> 10, j = idx & 1023;
    float s = 0.f;
#pragma unroll
    for (int f = 0; f < NFd; f++) s += x[n * NFd + f] * W[f * HCd + j];
    out[idx] = s;
}

// ---------------- W transpose+convert: Wt_h[n][k] = half(W[k][n]) -------
__global__ void k_cvtW(const float* __restrict__ W, __half* __restrict__ Wt) {
    __shared__ float t[32][33];
    int bx = blockIdx.x * 32, by = blockIdx.y * 32;
    int tx = threadIdx.x, ty = threadIdx.y;
#pragma unroll
    for (int j = 0; j < 32; j += 8) t[ty + j][tx] = W[(size_t)(by + ty + j) * HCd + bx + tx];
    __syncthreads();
#pragma unroll
    for (int j = 0; j < 32; j += 8)
        Wt[(size_t)(bx + ty + j) * HCd + by + tx] = __float2half_rn(t[tx][ty + j]);
}

// ---------------- fp16 mma.sync GEMM (2-stage, BK=32) -------------------
// C[M,1024] = A_h[M,1024] @ Wt_h^T ; A row-major half, B n-major half.
#define MM_BK 32
#define MM_NT (HCd / MM_BK)
#define MM_STR 40                       // smem stride in halves (32 + 8 pad)
#define MM_AH (128 * MM_STR)            // 5120 halves
#define MM_STAGEH (2 * MM_AH)           // A + B per stage, halves
#define MM_SMEM (2 * MM_STAGEH * 2)     // bytes = 40960

__device__ __forceinline__ uint32_t s2u(const void* p) {
    uint32_t a;
    asm("{ .reg .u64 t; cvta.to.shared.u64 t, %1; cvt.u32.u64 %0, t; }" : "=r"(a) : "l"(p));
    return a;
}

__device__ __forceinline__ void mma16(float* c, const uint32_t* a, const uint32_t* b) {
    asm volatile(
        "mma.sync.aligned.m16n8k16.row.col.f32.f16.f16.f32 "
        "{%0,%1,%2,%3}, {%4,%5,%6,%7}, {%8,%9}, {%0,%1,%2,%3};"
        : "+f"(c[0]), "+f"(c[1]), "+f"(c[2]), "+f"(c[3])
        : "r"(a[0]), "r"(a[1]), "r"(a[2]), "r"(a[3]), "r"(b[0]), "r"(b[1]));
}

__global__ __launch_bounds__(256)
void k_mma(const __half* __restrict__ A, const __half* __restrict__ Bt,
           float* __restrict__ C, int M) {
    extern __shared__ __align__(16) __half smem[];
    const int tid = threadIdx.x, wid = tid >> 5, lane = tid & 31;
    const int warp_m = wid & 3, warp_n = wid >> 2;
    const int row0 = blockIdx.y * 128, col0 = blockIdx.x * 128;
    const int lg = lane >> 2, lk = lane & 3;

    float acc[2][8][4];
#pragma unroll
    for (int mf = 0; mf < 2; mf++)
#pragma unroll
        for (int nf = 0; nf < 8; nf++)
#pragma unroll
            for (int q = 0; q < 4; q++) acc[mf][nf][q] = 0.f;

    // stage loader: A 128x32 half (row-major), B 128x32 half (n-major)
    auto load_stage = [&](int st, int k0) {
        __half* sA = smem + st * MM_STAGEH;
        __half* sB = sA + MM_AH;
#pragma unroll
        for (int i = 0; i < 2; i++) {
            int id = tid * 2 + i;
            int r = id >> 2, c8 = id & 3;
            uint32_t d = s2u(sA) + (r * MM_STR + c8 * 8) * 2;
            int gr = row0 + r;
            if (gr < M)
                asm volatile("cp.async.cg.shared.global [%0], [%1], 16;"
                             :: "r"(d), "l"(A + (size_t)gr * HCd + k0 + c8 * 8));
            else
                asm volatile("st.shared.v4.b32 [%0], {%1,%1,%1,%1};" :: "r"(d), "r"(0u) : "memory");
        }
#pragma unroll
        for (int i = 0; i < 2; i++) {
            int id = tid * 2 + i;
            int r = id >> 2, c8 = id & 3;
            uint32_t d = s2u(sB) + (r * MM_STR + c8 * 8) * 2;
            asm volatile("cp.async.cg.shared.global [%0], [%1], 16;"
                         :: "r"(d), "l"(Bt + (size_t)(col0 + r) * HCd + k0 + c8 * 8));
        }
    };

    load_stage(0, 0);
    asm volatile("cp.async.commit_group;" ::: "memory");

    for (int kt = 0; kt < MM_NT; kt++) {
        if (kt + 1 < MM_NT) {
            load_stage((kt + 1) & 1, (kt + 1) * MM_BK);
            asm volatile("cp.async.commit_group;" ::: "memory");
            asm volatile("cp.async.wait_group 1;" ::: "memory");
        } else {
            asm volatile("cp.async.wait_group 0;" ::: "memory");
        }
        __syncthreads();

        const __half* sA = smem + (kt & 1) * MM_STAGEH;
        const __half* sB = sA + MM_AH;
#pragma unroll
        for (int ks = 0; ks < 2; ks++) {
            int kb = ks * 16 + 2 * lk;
            uint32_t af[2][4], bf[8][2];
#pragma unroll
            for (int mf = 0; mf < 2; mf++) {
                int m = warp_m * 32 + mf * 16 + lg;
                af[mf][0] = *(const uint32_t*)&sA[m * MM_STR + kb];
                af[mf][1] = *(const uint32_t*)&sA[(m + 8) * MM_STR + kb];
                af[mf][2] = *(const uint32_t*)&sA[m * MM_STR + kb + 8];
                af[mf][3] = *(const uint32_t*)&sA[(m + 8) * MM_STR + kb + 8];
            }
#pragma unroll
            for (int nf = 0; nf < 8; nf++) {
                int n = warp_n * 64 + nf * 8 + lg;
                bf[nf][0] = *(const uint32_t*)&sB[n * MM_STR + kb];
                bf[nf][1] = *(const uint32_t*)&sB[n * MM_STR + kb + 8];
            }
#pragma unroll
            for (int mf = 0; mf < 2; mf++)
#pragma unroll
                for (int nf = 0; nf < 8; nf++) mma16(acc[mf][nf], af[mf], bf[nf]);
        }
        __syncthreads();
    }

#pragma unroll
    for (int mf = 0; mf < 2; mf++) {
        int r0 = row0 + warp_m * 32 + mf * 16 + lg;
        int r1 = r0 + 8;
#pragma unroll
        for (int nf = 0; nf < 8; nf++) {
            int ccol = col0 + warp_n * 64 + nf * 8 + 2 * lk;
            if (r0 < M) *(float2*)(C + (size_t)r0 * HCd + ccol) =
                make_float2(acc[mf][nf][0], acc[mf][nf][1]);
            if (r1 < M) *(float2*)(C + (size_t)r1 * HCd + ccol) =
                make_float2(acc[mf][nf][2], acc[mf][nf][3]);
        }
    }
}

// ---------------- attention pieces --------------------------------------
__global__ void k_attn(const float* __restrict__ xl, const float* __restrict__ a_s,
                       const float* __restrict__ a_d) {
    int gw = (blockIdx.x * blockDim.x + threadIdx.x) >> 5;
    int lane = threadIdx.x & 31;
    if (gw >= Nn * Hh) return;
    int n = gw >> 3, h = gw & 7;
    float4 xv = *(const float4*)(xl + (size_t)n * HCd + h * Cc + lane * 4);
    float4 sv = *(const float4*)(a_s + h * Cc + lane * 4);
    float4 dv = *(const float4*)(a_d + h * Cc + lane * 4);
    float s1 = xv.x * sv.x + xv.y * sv.y + xv.z * sv.z + xv.w * sv.w;
    float s2 = xv.x * dv.x + xv.y * dv.y + xv.z * dv.z + xv.w * dv.w;
#pragma unroll
    for (int o = 16; o; o >>= 1) {
        s1 += __shfl_xor_sync(0xffffffffu, s1, o);
        s2 += __shfl_xor_sync(0xffffffffu, s2, o);
    }
    if (lane == 0) {
        g_asrc[n * 8 + h] = s1;
        g_adst[n * 8 + h] = s2;
    }
}

__global__ void k_v(const float* __restrict__ We, const float* __restrict__ ae) {
    int w = threadIdx.x >> 5, lane = threadIdx.x & 31;
    if (w >= 24) return;
    int f = w >> 3, h = w & 7;
    float s = 0.f;
    for (int i = lane; i < Cc; i += 32) s += We[f * HCd + h * Cc + i] * ae[h * Cc + i];
#pragma unroll
    for (int o = 16; o; o >>= 1) s += __shfl_xor_sync(0xffffffffu, s, o);
    if (lane == 0) g_v[f * 8 + h] = s;
}

// block per node; warp = head; lane owns 4 consecutive cols.
// mode 0: write fp16 (feeds next GEMM); mode 1: write fp32 (feeds k_head)
__global__ __launch_bounds__(256) void k_agg(const float* __restrict__ xl,
                                             const float* __restrict__ bias,
                                             __half* __restrict__ outh,
                                             float* __restrict__ outf, int mode) {
    int n = blockIdx.x;
    int lane = threadIdx.x & 31;
    int h = threadIdx.x >> 5;
    int col = h * Cc + lane * 4;

    float vh0 = g_v[h], vh1 = g_v[8 + h], vh2 = g_v[16 + h];
    float adh = g_adst[n * 8 + h];
    float ash = g_asrc[n * 8 + h];
    float l0 = g_loop[n * 3 + 0], l1 = g_loop[n * 3 + 1], l2 = g_loop[n * 3 + 2];
    float c = lrelu(ash + adh + (l0 * vh0 + l1 * vh1 + l2 * vh2));

    // self contribution: exp(c - c) = 1
    float4 xv = *(const float4*)(xl + (size_t)n * HCd + col);
    float4 acc = xv;
    float den = 1.f;

    int s = g_off[n], tend = g_off[n + 1];
    for (int base = s; base < tend; base += 32) {
        int m = tend - base;
        if (m > 32) m = 32;
        float w = 0.f;
        int sn = 0;
        if (lane < m) {
            sn = g_csrc[base + lane];
            float4 q = g_cea4[base + lane];
            float asn = g_asrc[sn * 8 + h];
            float aeh = q.x * vh0 + q.y * vh1 + q.z * vh2;
            w = __expf(lrelu(asn + adh + aeh) - c);
        }
#pragma unroll 4
        for (int jj = 0; jj < m; jj++) {
            float wj = __shfl_sync(0xffffffffu, w, jj);
            int snj = __shfl_sync(0xffffffffu, sn, jj);
            float4 xr = *(const float4*)(xl + (size_t)snj * HCd + col);
            acc.x += wj * xr.x;
            acc.y += wj * xr.y;
            acc.z += wj * xr.z;
            acc.w += wj * xr.w;
            den += wj;
        }
    }

    float inv = 1.f / (den + 1e-16f);
    float4 v = make_float4(acc.x * inv, acc.y * inv, acc.z * inv, acc.w * inv);
    if (mode == 0) {
        float4 b = *(const float4*)(bias + col);
        v.x += b.x; v.y += b.y; v.z += b.z; v.w += b.w;
        v.x = v.x > 0.f ? v.x : expm1f(v.x);
        v.y = v.y > 0.f ? v.y : expm1f(v.y);
        v.z = v.z > 0.f ? v.z : expm1f(v.z);
        v.w = v.w > 0.f ? v.w : expm1f(v.w);
        __half2 p0 = __floats2half2_rn(v.x, v.y);
        __half2 p1 = __floats2half2_rn(v.z, v.w);
        uint2 pk;
        pk.x = *(uint32_t*)&p0;
        pk.y = *(uint32_t*)&p1;
        *(uint2*)(outh + (size_t)n * HCd + col) = pk;
    } else {
        *(float4*)(outf + (size_t)n * HCd + col) = v;
    }
}

__global__ void k_head(const float* __restrict__ tmp, const float* __restrict__ b4) {
    int idx = blockIdx.x * blockDim.x + threadIdx.x;
    if (idx >= Nn * Cc) return;
    int n = idx >> 7, c = idx & 127;
    float s = 0.f;
#pragma unroll
    for (int h = 0; h < 8; h++) s += tmp[(size_t)n * HCd + h * Cc + c];
    float v = s * 0.125f + b4[c];
    g_h4[idx] = v > 0.f ? v : expm1f(v);
}

__global__ void k_pool(const float* __restrict__ lw, const float* __restrict__ lb,
                       float* __restrict__ outp) {
    int g = blockIdx.x, c = threadIdx.x;
    int s = g_gstart[g], cnt = g_gcnt[g];
    float acc = 0.f;
    for (int i = 0; i < cnt; i++) acc += g_h4[(size_t)(s + i) * Cc + c];
    acc *= lw[c];
    __shared__ float red[128];
    red[c] = acc;
    __syncthreads();
    for (int o = 64; o; o >>= 1) {
        if (c < o) red[c] += red[c + o];
        __syncthreads();
    }
    if (c == 0) outp[g] = red[0] / fmaxf((float)cnt, 1.f) + lb[0];
}

// ---------------- launch -------------------------------------------------
static void* sym(const void* s) {
    void* p = nullptr;
    cudaGetSymbolAddress(&p, (const void*)s);
    return p;
}

extern "C" void kernel_launch(void* const* d_in, const int* in_sizes, int n_in,
                              void* d_out, int out_size) {
    (void)in_sizes; (void)n_in; (void)out_size;
    const float* x = (const float*)d_in[0];
    const int* ei = (const int*)d_in[1];
    const float* ea = (const float*)d_in[2];
    const int* batch = (const int*)d_in[3];
    const float *W[4], *We[4], *As_[4], *Ad_[4], *Ae_[4], *Bb[4];
    for (int l = 0; l < 4; l++) {
        W[l]   = (const float*)d_in[4 + 6 * l + 0];
        We[l]  = (const float*)d_in[4 + 6 * l + 1];
        As_[l] = (const float*)d_in[4 + 6 * l + 2];
        Ad_[l] = (const float*)d_in[4 + 6 * l + 3];
        Ae_[l] = (const float*)d_in[4 + 6 * l + 4];
        Bb[l]  = (const float*)d_in[4 + 6 * l + 5];
    }
    const float* lw = (const float*)d_in[28];
    const float* lb = (const float*)d_in[29];
    float* outp = (float*)d_out;

    float* xl = (float*)sym(&g_xl);
    __half* hAh = (__half*)sym(&g_hAh);
    __half* hBh = (__half*)sym(&g_hBh);
    float* hf = (float*)sym(&g_hf);
    __half* Wh = (__half*)sym(&g_Wh);

    cudaFuncSetAttribute(k_mma, cudaFuncAttributeMaxDynamicSharedMemorySize, MM_SMEM);

    cudaMemsetAsync(sym(&g_deg), 0, Nn * sizeof(int));
    cudaMemsetAsync(sym(&g_loopsum), 0, Nn * EFd * sizeof(float));
    cudaMemsetAsync(sym(&g_cur), 0, Nn * sizeof(int));
    cudaMemsetAsync(sym(&g_gcnt), 0, Gg * sizeof(int));
    k_initg<<<1, 32>>>();
    k_deg<<<(Ee + 255) / 256, 256>>>(ei, ea);
    k_scan<<<1, 256>>>();
    k_fill<<<(Ee + 255) / 256, 256>>>(ei, ea);
    k_loop<<<(Nn + 255) / 256, 256>>>();
    k_bounds<<<(Nn + 255) / 256, 256>>>(batch);

    for (int l = 0; l < 4; l++) {
        if (l == 0) {
            k_gemm_small<<<(Nn * HCd + 255) / 256, 256>>>(x, W[0], xl);
        } else {
            const __half* inp = (l == 1) ? hAh : ((l == 2) ? hBh : hAh);
            k_cvtW<<<dim3(32, 32), dim3(32, 8)>>>(W[l], Wh);
            k_mma<<<dim3(HCd / 128, (Nn + 127) / 128), 256, MM_SMEM>>>(inp, Wh, xl, Nn);
        }

        k_attn<<<(Nn * Hh * 32 + 255) / 256, 256>>>(xl, As_[l], Ad_[l]);
        k_v<<<1, 768>>>(We[l], Ae_[l]);
        __half* outh = (l == 0) ? hAh : ((l == 1) ? hBh : hAh);
        k_agg<<<Nn, 256>>>(xl, Bb[l], outh, hf, (l < 3) ? 0 : 1);
        if (l == 3) k_head<<<(Nn * Cc + 255) / 256, 256>>>(hf, Bb[3]);
    }
    k_pool<<<Gg, 128>>>(lw, lb, outp);
}